// round 15
// baseline (speedup 1.0000x reference)
#include <cuda_runtime.h>
#include <cuda_fp16.h>
#include <cuda_bf16.h>
#include <math.h>
#include <stdint.h>

#define NN 50000
#define NE 800000
#define IN_DIM 128
#define ED_DIM 32
#define NH 4
#define NC 32
#define HC 128
#define SCALE 0.17677669529663687f  /* 1/sqrt(32) */
#define HIST_BLOCKS 3125            /* NE/256 */
#define DECW_BLOCKS 192             /* 12*4096/256 */

// ---------------- scratch ----------------
// fp32 node features: 0:Q1 1:Q2 2:Qa 3:P1 4:P2 5:Pa 6:xin
__device__ float g_nf[7ll * NN * HC];
__device__ __align__(16) __half g_kvh[(long long)NN * 640];
__device__ __align__(16) __half g_eas[(long long)NE * 32];  // ea in CSR order, fp16
__device__ float g_Wc[HC * 2 * HC];
__device__ __align__(16) char g_Wt[12][65536];
__device__ int   g_cnt[NN];          // zero-init; re-zeroed by k_edge
__device__ int   g_cursor[NN];       // zero-init; re-zeroed by k_edge
__device__ int   g_done;             // zero-init; reset by scan block
__device__ int   g_rowptr[NN + 1];
__device__ int   g_esrc[NE];
__device__ float g_ud[NN * HC], g_ua[NN * HC];

// ---------------- cache-hinted memory ops ----------------
__device__ __forceinline__ uint64_t mkpol_last() {
    uint64_t pol;
    asm("createpolicy.fractional.L2::evict_last.b64 %0, 1.0;" : "=l"(pol));
    return pol;
}
__device__ __forceinline__ uint64_t mkpol_first() {
    uint64_t pol;
    asm("createpolicy.fractional.L2::evict_first.b64 %0, 1.0;" : "=l"(pol));
    return pol;
}
__device__ __forceinline__ uint2 ldg_pol8(const void* p, uint64_t pol) {
    uint2 v;
    asm volatile("ld.global.L2::cache_hint.v2.u32 {%0,%1}, [%2], %3;"
                 : "=r"(v.x), "=r"(v.y) : "l"(p), "l"(pol));
    return v;
}
__device__ __forceinline__ float4 ldg_pol16f(const void* p, uint64_t pol) {
    float4 v;
    asm volatile("ld.global.L2::cache_hint.v4.f32 {%0,%1,%2,%3}, [%4], %5;"
                 : "=f"(v.x), "=f"(v.y), "=f"(v.z), "=f"(v.w) : "l"(p), "l"(pol));
    return v;
}
__device__ __forceinline__ int ldg_pol4i(const void* p, uint64_t pol) {
    int v;
    asm volatile("ld.global.L2::cache_hint.u32 %0, [%1], %2;"
                 : "=r"(v) : "l"(p), "l"(pol));
    return v;
}
__device__ __forceinline__ void stg_cs16(void* p, float4 v) {
    asm volatile("st.global.cs.v4.f32 [%0], {%1,%2,%3,%4};"
                 :: "l"(p), "f"(v.x), "f"(v.y), "f"(v.z), "f"(v.w) : "memory");
}
__device__ __forceinline__ void stg_cs8(void* p, uint2 v) {
    asm volatile("st.global.cs.v2.u32 [%0], {%1,%2};"
                 :: "l"(p), "r"(v.x), "r"(v.y) : "memory");
}

// ============ HMMA machinery (bf16x3 split precision) ============
__device__ __forceinline__ uint32_t smem_to_u32(const void* p) {
    uint32_t a;
    asm("{ .reg .u64 t; cvta.to.shared.u64 t, %1; cvt.u32.u64 %0, t; }" : "=r"(a) : "l"(p));
    return a;
}
__device__ __forceinline__ void st_sw4(char* base, int row, int col, uint32_t lo, uint32_t hi) {
    uint32_t off = row * 256 + ((((col >> 3) ^ (row & 7))) << 4) + ((col & 7) << 1);
    *(uint2*)(base + off) = make_uint2(lo, hi);
}
__device__ __forceinline__ uint32_t lm_addr(uint32_t base, int row, int chunk) {
    return base + row * 256 + (((chunk) ^ (row & 7)) << 4);
}
__device__ __forceinline__ void ldm_x4(uint32_t* r, uint32_t addr) {
    asm volatile("ldmatrix.sync.aligned.m8n8.x4.shared.b16 {%0,%1,%2,%3}, [%4];"
                 : "=r"(r[0]), "=r"(r[1]), "=r"(r[2]), "=r"(r[3]) : "r"(addr));
}
__device__ __forceinline__ void mma_bf16(float* c, const uint32_t* a, uint32_t b0, uint32_t b1) {
    asm volatile(
        "mma.sync.aligned.m16n8k16.row.col.f32.bf16.bf16.f32 "
        "{%0,%1,%2,%3}, {%4,%5,%6,%7}, {%8,%9}, {%0,%1,%2,%3};"
        : "+f"(c[0]), "+f"(c[1]), "+f"(c[2]), "+f"(c[3])
        : "r"(a[0]), "r"(a[1]), "r"(a[2]), "r"(a[3]), "r"(b0), "r"(b1));
}
__device__ __forceinline__ void dec_store(char* hib, char* lob, int row, int c4, float4 f) {
    __nv_bfloat162 h0 = __floats2bfloat162_rn(f.x, f.y);
    __nv_bfloat162 h1 = __floats2bfloat162_rn(f.z, f.w);
    float2 hf0 = __bfloat1622float2(h0), hf1 = __bfloat1622float2(h1);
    __nv_bfloat162 l0 = __floats2bfloat162_rn(f.x - hf0.x, f.y - hf0.y);
    __nv_bfloat162 l1 = __floats2bfloat162_rn(f.z - hf1.x, f.w - hf1.y);
    st_sw4(hib, row, c4, *(uint32_t*)&h0, *(uint32_t*)&h1);
    st_sw4(lob, row, c4, *(uint32_t*)&l0, *(uint32_t*)&l1);
}
__device__ __forceinline__ void cp16(uint32_t dst, const void* src) {
    asm volatile("cp.async.cg.shared.global [%0], [%1], 16;" :: "r"(dst), "l"(src) : "memory");
}

__device__ __forceinline__ void mma_block(uint32_t aH, uint32_t aL, uint32_t wH, uint32_t wL,
                                          int m0, int n0, int lane, float acc[2][8][4]) {
#pragma unroll
    for (int ks = 0; ks < 8; ks++) {
        int kch = ks * 2;
        uint32_t ah[2][4], al[2][4];
#pragma unroll
        for (int mi = 0; mi < 2; mi++) {
            int row = m0 + mi * 16 + (lane & 15);
            int ch = kch + (lane >> 4);
            ldm_x4(ah[mi], lm_addr(aH, row, ch));
            ldm_x4(al[mi], lm_addr(aL, row, ch));
        }
        uint32_t bh[8][2], bl[8][2];
#pragma unroll
        for (int nj = 0; nj < 4; nj++) {
            int rowb = n0 + nj * 16 + (lane & 7) + ((lane >> 4) << 3);
            int ch = kch + ((lane >> 3) & 1);
            uint32_t r4[4];
            ldm_x4(r4, lm_addr(wH, rowb, ch));
            bh[nj * 2][0] = r4[0]; bh[nj * 2][1] = r4[1];
            bh[nj * 2 + 1][0] = r4[2]; bh[nj * 2 + 1][1] = r4[3];
            ldm_x4(r4, lm_addr(wL, rowb, ch));
            bl[nj * 2][0] = r4[0]; bl[nj * 2][1] = r4[1];
            bl[nj * 2 + 1][0] = r4[2]; bl[nj * 2 + 1][1] = r4[3];
        }
#pragma unroll
        for (int mi = 0; mi < 2; mi++)
#pragma unroll
            for (int ni = 0; ni < 8; ni++) {
                mma_bf16(acc[mi][ni], ah[mi], bh[ni][0], bh[ni][1]);
                mma_bf16(acc[mi][ni], ah[mi], bl[ni][0], bl[ni][1]);
                mma_bf16(acc[mi][ni], al[mi], bh[ni][0], bh[ni][1]);
            }
    }
}

// ---------------- launch 1: hist + last-block scan + decw(+inline compose) ----------------
__global__ __launch_bounds__(256) void k_mix(
    const int* __restrict__ ei,
    const float* W0, const float* W1, const float* W2, const float* W3,
    const float* W4, const float* W5, const float* W6, const float* W7,
    const float* W8) {
    int b = blockIdx.x;
    int tid = threadIdx.x;
    if (b < HIST_BLOCKS) {
        int e = b * 256 + tid;
        if (e < NE) atomicAdd(&g_cnt[ei[NE + e]], 1);
        __threadfence();
        __syncthreads();
        __shared__ int amlast;
        if (tid == 0) {
            int old = atomicAdd(&g_done, 1);
            amlast = (old == HIST_BLOCKS - 1);
        }
        __syncthreads();
        if (!amlast) return;
        // ---- scan (256 threads) ----
        __shared__ int wsum[8];
        int lane = tid & 31, wid = tid >> 5;
        int carry = 0;
        if (tid == 0) g_rowptr[0] = 0;
        for (int base = 0; base < NN; base += 256) {
            int i = base + tid;
            int x = (i < NN) ? g_cnt[i] : 0;
#pragma unroll
            for (int off = 1; off < 32; off <<= 1) {
                int y = __shfl_up_sync(0xffffffffu, x, off);
                if (lane >= off) x += y;
            }
            if (lane == 31) wsum[wid] = x;
            __syncthreads();
            if (tid < 8) {
                int w = wsum[tid];
#pragma unroll
                for (int off = 1; off < 8; off <<= 1) {
                    int y = __shfl_up_sync(0xffu, w, off);
                    if (tid >= off) w += y;
                }
                wsum[tid] = w;
            }
            __syncthreads();
            int incl = x + (wid > 0 ? wsum[wid - 1] : 0);
            if (i < NN) g_rowptr[i + 1] = carry + incl;
            carry += wsum[7];
            __syncthreads();
        }
        if (tid == 0) g_done = 0;
        return;
    }
    // ---- decw blocks (with inline compose for m >= 9) ----
    int idx = (b - HIST_BLOCKS) * 256 + tid;
    int m = idx >> 12, u = idx & 4095;
    int row = u >> 5, c4 = (u & 31) << 2;
    float4 f;
    if (m < 9) {
        const float* W;
        switch (m) {
            case 0: W = W0; break; case 1: W = W1; break; case 2: W = W2; break;
            case 3: W = W3; break; case 4: W = W4; break; case 5: W = W5; break;
            case 6: W = W6; break; case 7: W = W7; break; default: W = W8; break;
        }
        f = *(const float4*)&W[row * 128 + c4];
    } else {
        // M[row][k] = sum_c Wq[(h*32+c)*128+k] * Wkr[(h*32+c)*32+d]
        int mm = m - 9;
        int hh = row >> 5, dd = row & 31;
        const float* Wq  = (mm == 0) ? W0 : (mm == 1) ? W1 : W2;        // Wq1,Wq2,Wqa
        const float* Wkr;
        // Wkr pointers are passed via W-slots? No: need real Wkr pointers.
        // handled by extra params below
        Wkr = nullptr; (void)Wkr;
        float4 s = make_float4(0.f, 0.f, 0.f, 0.f);
        (void)Wq; (void)hh; (void)dd; (void)s;
        f = make_float4(0.f, 0.f, 0.f, 0.f);  // overwritten by k_mix2 path below
    }
    if (m < 9) dec_store(&g_Wt[m][0], &g_Wt[m][32768], row, c4, f);
}

// separate tiny kernel folded into k_mix grid is messy for Wkr params; do M in its own block range
__global__ __launch_bounds__(256) void k_mixM(
    const float* __restrict__ Wq1, const float* __restrict__ Wq2, const float* __restrict__ Wqa,
    const float* __restrict__ Wkr1, const float* __restrict__ Wkr2, const float* __restrict__ Wkra) {
    int idx = blockIdx.x * 256 + threadIdx.x;
    if (idx >= 3 * 4096) return;
    int mm = idx >> 12, u = idx & 4095;
    int row = u >> 5, c4 = (u & 31) << 2;
    int hh = row >> 5, dd = row & 31;
    const float* Wq  = (mm == 0) ? Wq1  : (mm == 1) ? Wq2  : Wqa;
    const float* Wkr = (mm == 0) ? Wkr1 : (mm == 1) ? Wkr2 : Wkra;
    float4 s = make_float4(0.f, 0.f, 0.f, 0.f);
#pragma unroll 4
    for (int c = 0; c < 32; c++) {
        float4 wq = *(const float4*)&Wq[(hh * 32 + c) * 128 + c4];
        float wk = Wkr[(hh * 32 + c) * 32 + dd];
        s.x = fmaf(wq.x, wk, s.x); s.y = fmaf(wq.y, wk, s.y);
        s.z = fmaf(wq.z, wk, s.z); s.w = fmaf(wq.w, wk, s.w);
    }
    int m = 9 + mm;
    dec_store(&g_Wt[m][0], &g_Wt[m][32768], row, c4, s);
}

__global__ void k_compose2(const float* __restrict__ Wproj, const float* __restrict__ Woutd,
                           const float* __restrict__ Wouta) {
    int idx = blockIdx.x * blockDim.x + threadIdx.x;
    if (idx >= 2 * HC * HC) return;
    int side = idx >> 14;
    int r = (idx >> 7) & 127;
    int k = idx & 127;
    const float* Wout = side ? Wouta : Woutd;
    float s = 0.f;
#pragma unroll 8
    for (int c = 0; c < 128; c++)
        s += Wproj[r * 256 + side * 128 + c] * Wout[c * 128 + k];
    g_Wc[r * 256 + side * 128 + k] = s;
}

// ---------------- launch 3: scatter + ea reorder fused ----------------
__global__ __launch_bounds__(256) void k_scatter_easort(const int* __restrict__ ei,
                                                        const float* __restrict__ ea) {
    __shared__ int spos[256];
    int tid = threadIdx.x;
    int e0 = blockIdx.x * 256;
    int e = e0 + tid;
    if (e < NE) {
        int dd = ei[NE + e];
        int pos = g_rowptr[dd] + atomicAdd(&g_cursor[dd], 1);
        g_esrc[pos] = ei[e];
        spos[tid] = pos;
    }
    __syncthreads();
    // 8 threads per edge: coalesced row read + 64B row write
    int sub = tid & 7;
#pragma unroll 1
    for (int pass = 0; pass < 8; pass++) {
        int le = pass * 32 + (tid >> 3);
        int ee = e0 + le;
        if (ee < NE) {
            int pos = spos[le];
            float4 v = *(const float4*)&ea[(long long)ee * 32 + sub * 4];
            __half2 a = __floats2half2_rn(v.x, v.y);
            __half2 bb = __floats2half2_rn(v.z, v.w);
            uint2 pk; pk.x = *(uint32_t*)&a; pk.y = *(uint32_t*)&bb;
            stg_cs8(&g_eas[(long long)pos * 32 + sub * 4], pk);
        }
    }
}

// ---------------- launch 2: node projections (pipelined HMMA) ----------------
#define NP_AH 0
#define NP_AL 32768
#define NP_W(b) (65536 + (b) * 65536)
#define NP_STAGE 196608
#define NP_STRIDE 132
#define NP_TOTAL (NP_STAGE + 32 * NP_STRIDE * 4)

__global__ __launch_bounds__(256, 1) void k_nodeproj_hmma(
    const float* __restrict__ x, const float* __restrict__ b_in) {
    extern __shared__ char smem[];
    uint32_t sb = smem_to_u32(smem);
    float* stage = (float*)(smem + NP_STAGE);
    int tid = threadIdx.x;
    int wid = tid >> 5, lane = tid & 31;
    int n0blk = blockIdx.x * 128;
    int m0 = (wid & 3) * 32;
    int n0 = (wid >> 2) * 64;

    {
        uint32_t dst = sb + NP_W(0);
        const char* src = g_Wt[0];
#pragma unroll
        for (int i = 0; i < 16; i++)
            cp16(dst + tid * 16 + i * 4096, src + tid * 16 + i * 4096);
        asm volatile("cp.async.commit_group;" ::: "memory");
    }

    for (int u = tid; u < 4096; u += 256) {
        int row = u >> 5, c4 = (u & 31) << 2;
        float4 f = make_float4(0.f, 0.f, 0.f, 0.f);
        if (n0blk + row < NN) f = *(const float4*)&x[(long long)(n0blk + row) * 128 + c4];
        dec_store(smem + NP_AH, smem + NP_AL, row, c4, f);
    }

    for (int m = 0; m < 12; m++) {
        if (m < 11) {
            uint32_t dst = sb + NP_W((m + 1) & 1);
            const char* src = g_Wt[m + 1];
#pragma unroll
            for (int i = 0; i < 16; i++)
                cp16(dst + tid * 16 + i * 4096, src + tid * 16 + i * 4096);
            asm volatile("cp.async.commit_group;" ::: "memory");
            asm volatile("cp.async.wait_group 1;" ::: "memory");
        } else {
            asm volatile("cp.async.wait_group 0;" ::: "memory");
        }
        __syncthreads();

        float acc[2][8][4];
#pragma unroll
        for (int i = 0; i < 2; i++)
#pragma unroll
            for (int j = 0; j < 8; j++)
#pragma unroll
                for (int q = 0; q < 4; q++) acc[i][j][q] = 0.f;

        uint32_t wH = sb + NP_W(m & 1);
        mma_block(sb + NP_AH, sb + NP_AL, wH, wH + 32768, m0, n0, lane, acc);

        int s32 = (m < 3) ? m : (m == 8 ? 6 : (m >= 9 ? m - 6 : -1));
        int s16 = (m >= 3 && m < 8) ? m - 3 : -1;
        const float* bias = (m == 8) ? b_in : nullptr;
#pragma unroll 1
        for (int rc = 0; rc < 4; rc++) {
            if ((wid & 3) == rc) {
#pragma unroll
                for (int mi = 0; mi < 2; mi++)
#pragma unroll
                    for (int ni = 0; ni < 8; ni++) {
                        int lr = mi * 16 + (lane >> 2);
                        int col = n0 + ni * 8 + (lane & 3) * 2;
                        stage[lr * NP_STRIDE + col]     = acc[mi][ni][0];
                        stage[lr * NP_STRIDE + col + 1] = acc[mi][ni][1];
                        stage[(lr + 8) * NP_STRIDE + col]     = acc[mi][ni][2];
                        stage[(lr + 8) * NP_STRIDE + col + 1] = acc[mi][ni][3];
                    }
            }
            __syncthreads();
#pragma unroll
            for (int i = 0; i < 4; i++) {
                int p = tid + i * 256;
                int r = p >> 5, c4 = (p & 31) << 2;
                float4 v = *(float4*)&stage[r * NP_STRIDE + c4];
                int n = n0blk + rc * 32 + r;
                if (n < NN) {
                    if (s16 >= 0) {
                        __half2 ha = __floats2half2_rn(v.x, v.y);
                        __half2 hb = __floats2half2_rn(v.z, v.w);
                        uint2 pk; pk.x = *(uint32_t*)&ha; pk.y = *(uint32_t*)&hb;
                        *(uint2*)&g_kvh[(long long)n * 640 + s16 * 128 + c4] = pk;
                    } else {
                        if (bias) {
                            float4 b = *(const float4*)&bias[c4];
                            v.x += b.x; v.y += b.y; v.z += b.z; v.w += b.w;
                        }
                        *(float4*)&g_nf[((long long)s32 * NN + n) * 128 + c4] = v;
                    }
                }
            }
            __syncthreads();
        }
    }
}

// ---------------- launch 4 (PROFILED): fused edge kernel ----------------
__global__ __launch_bounds__(256) void k_edge(const float* __restrict__ lamp,
                                              const float* __restrict__ Wvrd,
                                              const float* __restrict__ Wvra) {
    __shared__ float sbuf[8][288];
    int warp = (blockIdx.x * blockDim.x + threadIdx.x) >> 5;
    int lane = threadIdx.x & 31;
    if (warp >= NN) return;
    int wslot = threadIdx.x >> 5;
    int d = warp;
    int h = lane >> 3, cg = lane & 7;
    int f = h * 32 + cg * 4;
    // reset counters for next replay (after scatter consumed them this replay)
    if (lane == 0) { g_cnt[d] = 0; g_cursor[d] = 0; }
    int r0 = g_rowptr[d], r1 = g_rowptr[d + 1];
    float lam = __ldg(lamp);
    uint64_t polL = mkpol_last();
    uint64_t polF = mkpol_first();

    float4 q1 = ldg_pol16f(&g_nf[(0ll * NN + d) * 128 + f], polF);
    float4 q2 = ldg_pol16f(&g_nf[(1ll * NN + d) * 128 + f], polF);
    float4 qa = ldg_pol16f(&g_nf[(2ll * NN + d) * 128 + f], polF);
    float4 p1 = ldg_pol16f(&g_nf[(3ll * NN + d) * 128 + f], polF);
    float4 p2 = ldg_pol16f(&g_nf[(4ll * NN + d) * 128 + f], polF);
    float4 pa = ldg_pol16f(&g_nf[(5ll * NN + d) * 128 + f], polF);
    q1.x *= SCALE; q1.y *= SCALE; q1.z *= SCALE; q1.w *= SCALE;
    q2.x *= SCALE; q2.y *= SCALE; q2.z *= SCALE; q2.w *= SCALE;
    qa.x *= SCALE; qa.y *= SCALE; qa.z *= SCALE; qa.w *= SCALE;
    p1.x *= SCALE; p1.y *= SCALE; p1.z *= SCALE; p1.w *= SCALE;
    p2.x *= SCALE; p2.y *= SCALE; p2.z *= SCALE; p2.w *= SCALE;
    pa.x *= SCALE; pa.y *= SCALE; pa.z *= SCALE; pa.w *= SCALE;

    float z1 = 0.f, z2 = 0.f, z3 = 0.f;
    float hd1[4] = {0, 0, 0, 0}, hd2[4] = {0, 0, 0, 0}, ha4[4] = {0, 0, 0, 0};
    float sd1[4] = {0, 0, 0, 0}, sd2[4] = {0, 0, 0, 0}, sa4[4] = {0, 0, 0, 0};

    if (r0 < r1) {
        int last = r1 - 1;
        int sN = ldg_pol4i(&g_esrc[r0], polF);
        const __half* kvp = &g_kvh[(long long)sN * 640];
        uint2 k1u = ldg_pol8(kvp + f, polL);
        uint2 k2u = ldg_pol8(kvp + 128 + f, polL);
        uint2 kau = ldg_pol8(kvp + 256 + f, polL);
        uint2 vdu = ldg_pol8(kvp + 384 + f, polL);
        uint2 vau = ldg_pol8(kvp + 512 + f, polL);
        uint2 eau = ldg_pol8(&g_eas[(long long)r0 * 32 + cg * 4], polF);

        for (int idx = r0; idx < r1; idx++) {
            int nx = (idx + 1 <= last) ? idx + 1 : last;
            int sNN = ldg_pol4i(&g_esrc[nx], polF);
            const __half* kvpN = &g_kvh[(long long)sNN * 640];
            uint2 nk1 = ldg_pol8(kvpN + f, polL);
            uint2 nk2 = ldg_pol8(kvpN + 128 + f, polL);
            uint2 nka = ldg_pol8(kvpN + 256 + f, polL);
            uint2 nvd = ldg_pol8(kvpN + 384 + f, polL);
            uint2 nva = ldg_pol8(kvpN + 512 + f, polL);
            uint2 nea = ldg_pol8(&g_eas[(long long)nx * 32 + cg * 4], polF);

            float2 k1a = __half22float2(*(__half2*)&k1u.x), k1b = __half22float2(*(__half2*)&k1u.y);
            float2 k2a = __half22float2(*(__half2*)&k2u.x), k2b = __half22float2(*(__half2*)&k2u.y);
            float2 kaa = __half22float2(*(__half2*)&kau.x), kab = __half22float2(*(__half2*)&kau.y);
            float2 ea0 = __half22float2(*(__half2*)&eau.x), ea1 = __half22float2(*(__half2*)&eau.y);

            float t0 = q1.x * k1a.x + q1.y * k1a.y + q1.z * k1b.x + q1.w * k1b.y
                     + p1.x * ea0.x + p1.y * ea0.y + p1.z * ea1.x + p1.w * ea1.y;
            float t1 = q2.x * k2a.x + q2.y * k2a.y + q2.z * k2b.x + q2.w * k2b.y
                     + p2.x * ea0.x + p2.y * ea0.y + p2.z * ea1.x + p2.w * ea1.y;
            float t2 = qa.x * kaa.x + qa.y * kaa.y + qa.z * kab.x + qa.w * kab.y
                     + pa.x * ea0.x + pa.y * ea0.y + pa.z * ea1.x + pa.w * ea1.y;
#pragma unroll
            for (int off = 1; off < 8; off <<= 1) {
                t0 += __shfl_xor_sync(0xffffffffu, t0, off);
                t1 += __shfl_xor_sync(0xffffffffu, t1, off);
                t2 += __shfl_xor_sync(0xffffffffu, t2, off);
            }
            float e1 = __expf(t0), e2 = __expf(t1), e3 = __expf(t2);
            z1 += e1; z2 += e2; z3 += e3;

            float2 vda = __half22float2(*(__half2*)&vdu.x), vdb = __half22float2(*(__half2*)&vdu.y);
            float2 vaa = __half22float2(*(__half2*)&vau.x), vab = __half22float2(*(__half2*)&vau.y);

            hd1[0] = fmaf(vda.x, e1, hd1[0]); hd1[1] = fmaf(vda.y, e1, hd1[1]);
            hd1[2] = fmaf(vdb.x, e1, hd1[2]); hd1[3] = fmaf(vdb.y, e1, hd1[3]);
            hd2[0] = fmaf(vda.x, e2, hd2[0]); hd2[1] = fmaf(vda.y, e2, hd2[1]);
            hd2[2] = fmaf(vdb.x, e2, hd2[2]); hd2[3] = fmaf(vdb.y, e2, hd2[3]);
            ha4[0] = fmaf(vaa.x, e3, ha4[0]); ha4[1] = fmaf(vaa.y, e3, ha4[1]);
            ha4[2] = fmaf(vab.x, e3, ha4[2]); ha4[3] = fmaf(vab.y, e3, ha4[3]);
            sd1[0] = fmaf(ea0.x, e1, sd1[0]); sd1[1] = fmaf(ea0.y, e1, sd1[1]);
            sd1[2] = fmaf(ea1.x, e1, sd1[2]); sd1[3] = fmaf(ea1.y, e1, sd1[3]);
            sd2[0] = fmaf(ea0.x, e2, sd2[0]); sd2[1] = fmaf(ea0.y, e2, sd2[1]);
            sd2[2] = fmaf(ea1.x, e2, sd2[2]); sd2[3] = fmaf(ea1.y, e2, sd2[3]);
            sa4[0] = fmaf(ea0.x, e3, sa4[0]); sa4[1] = fmaf(ea0.y, e3, sa4[1]);
            sa4[2] = fmaf(ea1.x, e3, sa4[2]); sa4[3] = fmaf(ea1.y, e3, sa4[3]);

            k1u = nk1; k2u = nk2; kau = nka; vdu = nvd; vau = nva; eau = nea;
        }
    }

    float i1n = 1.f / (z1 + 1e-16f);
    float i2l = lam / (z2 + 1e-16f);
    float i3n = 1.f / (z3 + 1e-16f);

    float hd[4], ha[4], sd[4], sa[4];
#pragma unroll
    for (int i = 0; i < 4; i++) {
        hd[i] = hd1[i] * i1n - hd2[i] * i2l;
        sd[i] = sd1[i] * i1n - sd2[i] * i2l;
        ha[i] = ha4[i] * i3n;
        sa[i] = sa4[i] * i3n;
    }

    *(float4*)&sbuf[wslot][h * 36 + cg * 4] = make_float4(sd[0], sd[1], sd[2], sd[3]);
    *(float4*)&sbuf[wslot][144 + h * 36 + cg * 4] = make_float4(sa[0], sa[1], sa[2], sa[3]);
    __syncwarp();

    const float* sdp = &sbuf[wslot][h * 36];
    const float* sap = &sbuf[wslot][144 + h * 36];
    float ud[4], ua[4];
#pragma unroll
    for (int i = 0; i < 4; i++) { ud[i] = hd[i]; ua[i] = ha[i]; }
#pragma unroll
    for (int i = 0; i < 4; i++) {
        const float4* wd = (const float4*)&Wvrd[(f + i) * 32];
        const float4* wa = (const float4*)&Wvra[(f + i) * 32];
        float accd = 0.f, acca = 0.f;
#pragma unroll
        for (int q = 0; q < 8; q++) {
            float4 w4 = __ldg(&wd[q]);
            float4 s4 = *(const float4*)&sdp[q * 4];
            accd += w4.x * s4.x + w4.y * s4.y + w4.z * s4.z + w4.w * s4.w;
            float4 w4a = __ldg(&wa[q]);
            float4 s4a = *(const float4*)&sap[q * 4];
            acca += w4a.x * s4a.x + w4a.y * s4a.y + w4a.z * s4a.z + w4a.w * s4a.w;
        }
        ud[i] += accd; ua[i] += acca;
    }
    stg_cs16(&g_ud[d * 128 + f], make_float4(ud[0], ud[1], ud[2], ud[3]));
    stg_cs16(&g_ua[d * 128 + f], make_float4(ua[0], ua[1], ua[2], ua[3]));
}

// ---------------- final HMMA ----------------
#define F_AH 0
#define F_AL 32768
#define F_WH 65536
#define F_WL 98304
#define F_STAGE 131072
#define F_STRIDE 132
#define F_TOTAL (F_STAGE + 128 * F_STRIDE * 4)

__global__ __launch_bounds__(256, 1) void k_final_hmma(
    const float* __restrict__ bproj, const float* __restrict__ rms_w,
    float* __restrict__ out) {
    extern __shared__ char smem[];
    uint32_t sb = smem_to_u32(smem);
    float* stage = (float*)(smem + F_STAGE);
    int tid = threadIdx.x;
    int wid = tid >> 5, lane = tid & 31;
    int n0blk = blockIdx.x * 128;
    int m0 = (wid & 3) * 32;
    int n0 = (wid >> 2) * 64;

    float acc[2][8][4];
#pragma unroll
    for (int i = 0; i < 2; i++)
#pragma unroll
        for (int j = 0; j < 8; j++)
#pragma unroll
            for (int q = 0; q < 4; q++) acc[i][j][q] = 0.f;

    for (int kh = 0; kh < 2; kh++) {
        const float* A = kh ? g_ua : g_ud;
        for (int u = tid; u < 4096; u += 256) {
            int row = u >> 5, c4 = (u & 31) << 2;
            float4 fv = make_float4(0.f, 0.f, 0.f, 0.f);
            if (n0blk + row < NN) fv = *(const float4*)&A[(long long)(n0blk + row) * 128 + c4];
            dec_store(smem + F_AH, smem + F_AL, row, c4, fv);
        }
        for (int u = tid; u < 4096; u += 256) {
            int row = u >> 5, c4 = (u & 31) << 2;
            float4 fv = *(const float4*)&g_Wc[row * 256 + kh * 128 + c4];
            dec_store(smem + F_WH, smem + F_WL, row, c4, fv);
        }
        __syncthreads();
        mma_block(sb + F_AH, sb + F_AL, sb + F_WH, sb + F_WL, m0, n0, lane, acc);
        __syncthreads();
    }
#pragma unroll
    for (int mi = 0; mi < 2; mi++)
#pragma unroll
        for (int ni = 0; ni < 8; ni++) {
            int row = m0 + mi * 16 + (lane >> 2);
            int col = n0 + ni * 8 + (lane & 3) * 2;
            stage[row * F_STRIDE + col]     = acc[mi][ni][0];
            stage[row * F_STRIDE + col + 1] = acc[mi][ni][1];
            stage[(row + 8) * F_STRIDE + col]     = acc[mi][ni][2];
            stage[(row + 8) * F_STRIDE + col + 1] = acc[mi][ni][3];
        }
    __syncthreads();

    float4 bp = *(const float4*)&bproj[lane * 4];
    float4 rw = *(const float4*)&rms_w[lane * 4];
#pragma unroll 1
    for (int rr = 0; rr < 16; rr++) {
        int r = wid * 16 + rr;
        int n = n0blk + r;
        float4 v = *(float4*)&stage[r * F_STRIDE + lane * 4];
        float4 xi = make_float4(0.f, 0.f, 0.f, 0.f);
        if (n < NN) xi = *(const float4*)&g_nf[(6ll * NN + n) * 128 + lane * 4];
        v.x += bp.x + xi.x; v.y += bp.y + xi.y;
        v.z += bp.z + xi.z; v.w += bp.w + xi.w;
        float ss = v.x * v.x + v.y * v.y + v.z * v.z + v.w * v.w;
#pragma unroll
        for (int off = 16; off > 0; off >>= 1)
            ss += __shfl_xor_sync(0xffffffffu, ss, off);
        float rn = rsqrtf(ss * (1.f / 128.f) + 1e-6f);
        if (n < NN) {
            float4 o = make_float4(v.x * rn * rw.x, v.y * rn * rw.y,
                                   v.z * rn * rw.z, v.w * rn * rw.w);
            *(float4*)&out[(long long)n * 128 + lane * 4] = o;
        }
    }
}

// ---------------- launch ----------------
extern "C" void kernel_launch(void* const* d_in, const int* in_sizes, int n_in,
                              void* d_out, int out_size) {
    const float* x     = (const float*)d_in[0];
    const int*   ei    = (const int*)d_in[1];
    const float* ea    = (const float*)d_in[2];
    const float* Wq1   = (const float*)d_in[3];
    const float* Wq2   = (const float*)d_in[4];
    const float* Wk1   = (const float*)d_in[5];
    const float* Wk2   = (const float*)d_in[6];
    const float* Wvd   = (const float*)d_in[7];
    const float* Wkr1  = (const float*)d_in[8];
    const float* Wkr2  = (const float*)d_in[9];
    const float* Wvrd  = (const float*)d_in[10];
    const float* Woutd = (const float*)d_in[11];
    const float* lam   = (const float*)d_in[12];
    const float* Wqa   = (const float*)d_in[13];
    const float* Wka   = (const float*)d_in[14];
    const float* Wva   = (const float*)d_in[15];
    const float* Wkra  = (const float*)d_in[16];
    const float* Wvra  = (const float*)d_in[17];
    const float* Wouta = (const float*)d_in[18];
    const float* Wproj = (const float*)d_in[19];
    const float* bproj = (const float*)d_in[20];
    const float* Win   = (const float*)d_in[21];
    const float* b_in  = (const float*)d_in[22];
    const float* rms_w = (const float*)d_in[23];
    float* out = (float*)d_out;

    int mtile = (NN + 127) / 128;  // 391

    cudaFuncSetAttribute(k_nodeproj_hmma, cudaFuncAttributeMaxDynamicSharedMemorySize, NP_TOTAL);
    cudaFuncSetAttribute(k_final_hmma, cudaFuncAttributeMaxDynamicSharedMemorySize, F_TOTAL);

    // 1: hist (+last-block scan) and decw for the 9 raw weights
    k_mix<<<HIST_BLOCKS + DECW_BLOCKS, 256>>>(ei, Wq1, Wq2, Wqa, Wk1, Wk2, Wka, Wvd, Wva, Win);
    // 2: composed-M decomposition (tiny) — counts as launch 2
    k_mixM<<<(3 * 4096 + 255) / 256, 256>>>(Wq1, Wq2, Wqa, Wkr1, Wkr2, Wkra);
    // hmm: this makes nodeproj 3rd and edge 5th. Fold: launch k_mixM FIRST (independent).
    // (ordering fixed below — see actual sequence)
    k_nodeproj_hmma<<<mtile, 256, NP_TOTAL>>>(x, b_in);
    k_scatter_easort<<<HIST_BLOCKS, 256>>>(ei, ea);
    k_edge<<<(NN * 32 + 255) / 256, 256>>>(lam, Wvrd, Wvra);
    k_compose2<<<(2 * HC * HC + 255) / 256, 256>>>(Wproj, Woutd, Wouta);
    k_final_hmma<<<mtile, 256, F_TOTAL>>>(bproj, rms_w, out);
}

// round 16
// speedup vs baseline: 1.1146x; 1.1146x over previous
#include <cuda_runtime.h>
#include <cuda_fp16.h>
#include <cuda_bf16.h>
#include <math.h>
#include <stdint.h>

#define NN 50000
#define NE 800000
#define IN_DIM 128
#define ED_DIM 32
#define NH 4
#define NC 32
#define HC 128
#define SCALE 0.17677669529663687f  /* 1/sqrt(32) */
#define HB 782                      /* hist blocks @1024 thr: ceil(NE/1024) */
#define DB 48                       /* decw blocks @1024 thr: 12*4096/1024 */

// ---------------- scratch ----------------
// fp32 node features: 0:Q1 1:Q2 2:Qa 3:P1 4:P2 5:Pa 6:xin
__device__ float g_nf[7ll * NN * HC];
__device__ __align__(16) __half g_kvh[(long long)NN * 640];
__device__ __align__(16) __half g_eas[(long long)NE * 32];
__device__ float g_Wc[HC * 2 * HC];
__device__ __align__(16) char g_Wt[12][65536];
__device__ int   g_cnt[NN];      // zero-init; re-zeroed by k_edge each run
__device__ int   g_cursor[NN];   // zero-init; re-zeroed by k_edge each run
__device__ int   g_done;         // zero-init; reset by scan block
__device__ int   g_rowptr[NN + 1];
__device__ int   g_esrc[NE];
__device__ float g_ud[NN * HC], g_ua[NN * HC];

// ---------------- cache-hinted memory ops ----------------
__device__ __forceinline__ uint64_t mkpol_last() {
    uint64_t pol;
    asm("createpolicy.fractional.L2::evict_last.b64 %0, 1.0;" : "=l"(pol));
    return pol;
}
__device__ __forceinline__ uint64_t mkpol_first() {
    uint64_t pol;
    asm("createpolicy.fractional.L2::evict_first.b64 %0, 1.0;" : "=l"(pol));
    return pol;
}
__device__ __forceinline__ uint2 ldg_pol8(const void* p, uint64_t pol) {
    uint2 v;
    asm volatile("ld.global.L2::cache_hint.v2.u32 {%0,%1}, [%2], %3;"
                 : "=r"(v.x), "=r"(v.y) : "l"(p), "l"(pol));
    return v;
}
__device__ __forceinline__ float4 ldg_pol16f(const void* p, uint64_t pol) {
    float4 v;
    asm volatile("ld.global.L2::cache_hint.v4.f32 {%0,%1,%2,%3}, [%4], %5;"
                 : "=f"(v.x), "=f"(v.y), "=f"(v.z), "=f"(v.w) : "l"(p), "l"(pol));
    return v;
}
__device__ __forceinline__ int ldg_pol4i(const void* p, uint64_t pol) {
    int v;
    asm volatile("ld.global.L2::cache_hint.u32 %0, [%1], %2;"
                 : "=r"(v) : "l"(p), "l"(pol));
    return v;
}
__device__ __forceinline__ void stg_cs16(void* p, float4 v) {
    asm volatile("st.global.cs.v4.f32 [%0], {%1,%2,%3,%4};"
                 :: "l"(p), "f"(v.x), "f"(v.y), "f"(v.z), "f"(v.w) : "memory");
}
__device__ __forceinline__ void stg_cs8(void* p, uint2 v) {
    asm volatile("st.global.cs.v2.u32 [%0], {%1,%2};"
                 :: "l"(p), "r"(v.x), "r"(v.y) : "memory");
}

// ============ HMMA machinery (bf16x3 split precision) ============
__device__ __forceinline__ uint32_t smem_to_u32(const void* p) {
    uint32_t a;
    asm("{ .reg .u64 t; cvta.to.shared.u64 t, %1; cvt.u32.u64 %0, t; }" : "=r"(a) : "l"(p));
    return a;
}
__device__ __forceinline__ void st_sw4(char* base, int row, int col, uint32_t lo, uint32_t hi) {
    uint32_t off = row * 256 + ((((col >> 3) ^ (row & 7))) << 4) + ((col & 7) << 1);
    *(uint2*)(base + off) = make_uint2(lo, hi);
}
__device__ __forceinline__ uint32_t lm_addr(uint32_t base, int row, int chunk) {
    return base + row * 256 + (((chunk) ^ (row & 7)) << 4);
}
__device__ __forceinline__ void ldm_x4(uint32_t* r, uint32_t addr) {
    asm volatile("ldmatrix.sync.aligned.m8n8.x4.shared.b16 {%0,%1,%2,%3}, [%4];"
                 : "=r"(r[0]), "=r"(r[1]), "=r"(r[2]), "=r"(r[3]) : "r"(addr));
}
__device__ __forceinline__ void mma_bf16(float* c, const uint32_t* a, uint32_t b0, uint32_t b1) {
    asm volatile(
        "mma.sync.aligned.m16n8k16.row.col.f32.bf16.bf16.f32 "
        "{%0,%1,%2,%3}, {%4,%5,%6,%7}, {%8,%9}, {%0,%1,%2,%3};"
        : "+f"(c[0]), "+f"(c[1]), "+f"(c[2]), "+f"(c[3])
        : "r"(a[0]), "r"(a[1]), "r"(a[2]), "r"(a[3]), "r"(b0), "r"(b1));
}
__device__ __forceinline__ void dec_store(char* hib, char* lob, int row, int c4, float4 f) {
    __nv_bfloat162 h0 = __floats2bfloat162_rn(f.x, f.y);
    __nv_bfloat162 h1 = __floats2bfloat162_rn(f.z, f.w);
    float2 hf0 = __bfloat1622float2(h0), hf1 = __bfloat1622float2(h1);
    __nv_bfloat162 l0 = __floats2bfloat162_rn(f.x - hf0.x, f.y - hf0.y);
    __nv_bfloat162 l1 = __floats2bfloat162_rn(f.z - hf1.x, f.w - hf1.y);
    st_sw4(hib, row, c4, *(uint32_t*)&h0, *(uint32_t*)&h1);
    st_sw4(lob, row, c4, *(uint32_t*)&l0, *(uint32_t*)&l1);
}
__device__ __forceinline__ void cp16(uint32_t dst, const void* src) {
    asm volatile("cp.async.cg.shared.global [%0], [%1], 16;" :: "r"(dst), "l"(src) : "memory");
}

__device__ __forceinline__ void mma_block(uint32_t aH, uint32_t aL, uint32_t wH, uint32_t wL,
                                          int m0, int n0, int lane, float acc[2][8][4]) {
#pragma unroll
    for (int ks = 0; ks < 8; ks++) {
        int kch = ks * 2;
        uint32_t ah[2][4], al[2][4];
#pragma unroll
        for (int mi = 0; mi < 2; mi++) {
            int row = m0 + mi * 16 + (lane & 15);
            int ch = kch + (lane >> 4);
            ldm_x4(ah[mi], lm_addr(aH, row, ch));
            ldm_x4(al[mi], lm_addr(aL, row, ch));
        }
        uint32_t bh[8][2], bl[8][2];
#pragma unroll
        for (int nj = 0; nj < 4; nj++) {
            int rowb = n0 + nj * 16 + (lane & 7) + ((lane >> 4) << 3);
            int ch = kch + ((lane >> 3) & 1);
            uint32_t r4[4];
            ldm_x4(r4, lm_addr(wH, rowb, ch));
            bh[nj * 2][0] = r4[0]; bh[nj * 2][1] = r4[1];
            bh[nj * 2 + 1][0] = r4[2]; bh[nj * 2 + 1][1] = r4[3];
            ldm_x4(r4, lm_addr(wL, rowb, ch));
            bl[nj * 2][0] = r4[0]; bl[nj * 2][1] = r4[1];
            bl[nj * 2 + 1][0] = r4[2]; bl[nj * 2 + 1][1] = r4[3];
        }
#pragma unroll
        for (int mi = 0; mi < 2; mi++)
#pragma unroll
            for (int ni = 0; ni < 8; ni++) {
                mma_bf16(acc[mi][ni], ah[mi], bh[ni][0], bh[ni][1]);
                mma_bf16(acc[mi][ni], ah[mi], bl[ni][0], bl[ni][1]);
                mma_bf16(acc[mi][ni], al[mi], bh[ni][0], bh[ni][1]);
            }
    }
}

// ---------------- launch 1: hist + last-block 1024-wide scan + decw(+M compose) ----------------
__global__ __launch_bounds__(1024) void k_mix(
    const int* __restrict__ ei,
    const float* W0, const float* W1, const float* W2, const float* W3,
    const float* W4, const float* W5, const float* W6, const float* W7,
    const float* W8,
    const float* __restrict__ Wkr1, const float* __restrict__ Wkr2,
    const float* __restrict__ Wkra) {
    int b = blockIdx.x;
    int tid = threadIdx.x;
    if (b < HB) {
        int e = b * 1024 + tid;
        if (e < NE) atomicAdd(&g_cnt[ei[NE + e]], 1);
        __threadfence();
        __syncthreads();
        __shared__ int amlast;
        if (tid == 0) {
            int old = atomicAdd(&g_done, 1);
            amlast = (old == HB - 1);
        }
        __syncthreads();
        if (!amlast) return;
        // ---- 1024-wide scan ----
        __shared__ int wsum[32];
        int lane = tid & 31, wid = tid >> 5;
        int carry = 0;
        if (tid == 0) g_rowptr[0] = 0;
        for (int base = 0; base < NN; base += 1024) {
            int i = base + tid;
            int x = (i < NN) ? g_cnt[i] : 0;
#pragma unroll
            for (int off = 1; off < 32; off <<= 1) {
                int y = __shfl_up_sync(0xffffffffu, x, off);
                if (lane >= off) x += y;
            }
            if (lane == 31) wsum[wid] = x;
            __syncthreads();
            if (wid == 0) {
                int w = wsum[lane];
#pragma unroll
                for (int off = 1; off < 32; off <<= 1) {
                    int y = __shfl_up_sync(0xffffffffu, w, off);
                    if (lane >= off) w += y;
                }
                wsum[lane] = w;
            }
            __syncthreads();
            int incl = x + (wid > 0 ? wsum[wid - 1] : 0);
            if (i < NN) g_rowptr[i + 1] = carry + incl;
            carry += wsum[31];
            __syncthreads();
        }
        if (tid == 0) g_done = 0;
        return;
    }
    // ---- decw (+ inline M compose for m >= 9) ----
    int idx = (b - HB) * 1024 + tid;
    int m = idx >> 12, u = idx & 4095;
    int row = u >> 5, c4 = (u & 31) << 2;
    float4 f;
    if (m < 9) {
        const float* W;
        switch (m) {
            case 0: W = W0; break; case 1: W = W1; break; case 2: W = W2; break;
            case 3: W = W3; break; case 4: W = W4; break; case 5: W = W5; break;
            case 6: W = W6; break; case 7: W = W7; break; default: W = W8; break;
        }
        f = *(const float4*)&W[row * 128 + c4];
    } else {
        int mm = m - 9;
        int hh = row >> 5, dd = row & 31;
        const float* Wq  = (mm == 0) ? W0   : (mm == 1) ? W1   : W2;
        const float* Wkr = (mm == 0) ? Wkr1 : (mm == 1) ? Wkr2 : Wkra;
        float4 s = make_float4(0.f, 0.f, 0.f, 0.f);
#pragma unroll 4
        for (int c = 0; c < 32; c++) {
            float4 wq = *(const float4*)&Wq[(hh * 32 + c) * 128 + c4];
            float wk = Wkr[(hh * 32 + c) * 32 + dd];
            s.x = fmaf(wq.x, wk, s.x); s.y = fmaf(wq.y, wk, s.y);
            s.z = fmaf(wq.z, wk, s.z); s.w = fmaf(wq.w, wk, s.w);
        }
        f = s;
    }
    dec_store(&g_Wt[m][0], &g_Wt[m][32768], row, c4, f);
}

__global__ void k_compose2(const float* __restrict__ Wproj, const float* __restrict__ Woutd,
                           const float* __restrict__ Wouta) {
    int idx = blockIdx.x * blockDim.x + threadIdx.x;
    if (idx >= 2 * HC * HC) return;
    int side = idx >> 14;
    int r = (idx >> 7) & 127;
    int k = idx & 127;
    const float* Wout = side ? Wouta : Woutd;
    float s = 0.f;
#pragma unroll 8
    for (int c = 0; c < 128; c++)
        s += Wproj[r * 256 + side * 128 + c] * Wout[c * 128 + k];
    g_Wc[r * 256 + side * 128 + k] = s;
}

// ---------------- launch 3: scatter + ea reorder fused ----------------
__global__ __launch_bounds__(256) void k_scatter_easort(const int* __restrict__ ei,
                                                        const float* __restrict__ ea) {
    __shared__ int spos[256];
    int tid = threadIdx.x;
    int e0 = blockIdx.x * 256;
    int e = e0 + tid;
    if (e < NE) {
        int dd = ei[NE + e];
        int pos = g_rowptr[dd] + atomicAdd(&g_cursor[dd], 1);
        g_esrc[pos] = ei[e];
        spos[tid] = pos;
    }
    __syncthreads();
    int sub = tid & 7;
#pragma unroll 1
    for (int pass = 0; pass < 8; pass++) {
        int le = pass * 32 + (tid >> 3);
        int ee = e0 + le;
        if (ee < NE) {
            int pos = spos[le];
            float4 v = *(const float4*)&ea[(long long)ee * 32 + sub * 4];
            __half2 a = __floats2half2_rn(v.x, v.y);
            __half2 bb = __floats2half2_rn(v.z, v.w);
            uint2 pk; pk.x = *(uint32_t*)&a; pk.y = *(uint32_t*)&bb;
            stg_cs8(&g_eas[(long long)pos * 32 + sub * 4], pk);
        }
    }
}

// ---------------- launch 2: node projections (pipelined HMMA) ----------------
#define NP_AH 0
#define NP_AL 32768
#define NP_W(b) (65536 + (b) * 65536)
#define NP_STAGE 196608
#define NP_STRIDE 132
#define NP_TOTAL (NP_STAGE + 32 * NP_STRIDE * 4)

__global__ __launch_bounds__(256, 1) void k_nodeproj_hmma(
    const float* __restrict__ x, const float* __restrict__ b_in) {
    extern __shared__ char smem[];
    uint32_t sb = smem_to_u32(smem);
    float* stage = (float*)(smem + NP_STAGE);
    int tid = threadIdx.x;
    int wid = tid >> 5, lane = tid & 31;
    int n0blk = blockIdx.x * 128;
    int m0 = (wid & 3) * 32;
    int n0 = (wid >> 2) * 64;

    {
        uint32_t dst = sb + NP_W(0);
        const char* src = g_Wt[0];
#pragma unroll
        for (int i = 0; i < 16; i++)
            cp16(dst + tid * 16 + i * 4096, src + tid * 16 + i * 4096);
        asm volatile("cp.async.commit_group;" ::: "memory");
    }

    for (int u = tid; u < 4096; u += 256) {
        int row = u >> 5, c4 = (u & 31) << 2;
        float4 f = make_float4(0.f, 0.f, 0.f, 0.f);
        if (n0blk + row < NN) f = *(const float4*)&x[(long long)(n0blk + row) * 128 + c4];
        dec_store(smem + NP_AH, smem + NP_AL, row, c4, f);
    }

    for (int m = 0; m < 12; m++) {
        if (m < 11) {
            uint32_t dst = sb + NP_W((m + 1) & 1);
            const char* src = g_Wt[m + 1];
#pragma unroll
            for (int i = 0; i < 16; i++)
                cp16(dst + tid * 16 + i * 4096, src + tid * 16 + i * 4096);
            asm volatile("cp.async.commit_group;" ::: "memory");
            asm volatile("cp.async.wait_group 1;" ::: "memory");
        } else {
            asm volatile("cp.async.wait_group 0;" ::: "memory");
        }
        __syncthreads();

        float acc[2][8][4];
#pragma unroll
        for (int i = 0; i < 2; i++)
#pragma unroll
            for (int j = 0; j < 8; j++)
#pragma unroll
                for (int q = 0; q < 4; q++) acc[i][j][q] = 0.f;

        uint32_t wH = sb + NP_W(m & 1);
        mma_block(sb + NP_AH, sb + NP_AL, wH, wH + 32768, m0, n0, lane, acc);

        int s32 = (m < 3) ? m : (m == 8 ? 6 : (m >= 9 ? m - 6 : -1));
        int s16 = (m >= 3 && m < 8) ? m - 3 : -1;
        const float* bias = (m == 8) ? b_in : nullptr;
#pragma unroll 1
        for (int rc = 0; rc < 4; rc++) {
            if ((wid & 3) == rc) {
#pragma unroll
                for (int mi = 0; mi < 2; mi++)
#pragma unroll
                    for (int ni = 0; ni < 8; ni++) {
                        int lr = mi * 16 + (lane >> 2);
                        int col = n0 + ni * 8 + (lane & 3) * 2;
                        stage[lr * NP_STRIDE + col]     = acc[mi][ni][0];
                        stage[lr * NP_STRIDE + col + 1] = acc[mi][ni][1];
                        stage[(lr + 8) * NP_STRIDE + col]     = acc[mi][ni][2];
                        stage[(lr + 8) * NP_STRIDE + col + 1] = acc[mi][ni][3];
                    }
            }
            __syncthreads();
#pragma unroll
            for (int i = 0; i < 4; i++) {
                int p = tid + i * 256;
                int r = p >> 5, c4 = (p & 31) << 2;
                float4 v = *(float4*)&stage[r * NP_STRIDE + c4];
                int n = n0blk + rc * 32 + r;
                if (n < NN) {
                    if (s16 >= 0) {
                        __half2 ha = __floats2half2_rn(v.x, v.y);
                        __half2 hb = __floats2half2_rn(v.z, v.w);
                        uint2 pk; pk.x = *(uint32_t*)&ha; pk.y = *(uint32_t*)&hb;
                        *(uint2*)&g_kvh[(long long)n * 640 + s16 * 128 + c4] = pk;
                    } else {
                        if (bias) {
                            float4 b = *(const float4*)&bias[c4];
                            v.x += b.x; v.y += b.y; v.z += b.z; v.w += b.w;
                        }
                        *(float4*)&g_nf[((long long)s32 * NN + n) * 128 + c4] = v;
                    }
                }
            }
            __syncthreads();
        }
    }
}

// ---------------- launch 4 (PROFILED): fused edge kernel ----------------
__global__ __launch_bounds__(256) void k_edge(const float* __restrict__ lamp,
                                              const float* __restrict__ Wvrd,
                                              const float* __restrict__ Wvra) {
    __shared__ float sbuf[8][288];
    int warp = (blockIdx.x * blockDim.x + threadIdx.x) >> 5;
    int lane = threadIdx.x & 31;
    if (warp >= NN) return;
    int wslot = threadIdx.x >> 5;
    int d = warp;
    int h = lane >> 3, cg = lane & 7;
    int f = h * 32 + cg * 4;
    if (lane == 0) { g_cnt[d] = 0; g_cursor[d] = 0; }
    int r0 = g_rowptr[d], r1 = g_rowptr[d + 1];
    float lam = __ldg(lamp);
    uint64_t polL = mkpol_last();
    uint64_t polF = mkpol_first();

    float4 q1 = ldg_pol16f(&g_nf[(0ll * NN + d) * 128 + f], polF);
    float4 q2 = ldg_pol16f(&g_nf[(1ll * NN + d) * 128 + f], polF);
    float4 qa = ldg_pol16f(&g_nf[(2ll * NN + d) * 128 + f], polF);
    float4 p1 = ldg_pol16f(&g_nf[(3ll * NN + d) * 128 + f], polF);
    float4 p2 = ldg_pol16f(&g_nf[(4ll * NN + d) * 128 + f], polF);
    float4 pa = ldg_pol16f(&g_nf[(5ll * NN + d) * 128 + f], polF);
    q1.x *= SCALE; q1.y *= SCALE; q1.z *= SCALE; q1.w *= SCALE;
    q2.x *= SCALE; q2.y *= SCALE; q2.z *= SCALE; q2.w *= SCALE;
    qa.x *= SCALE; qa.y *= SCALE; qa.z *= SCALE; qa.w *= SCALE;
    p1.x *= SCALE; p1.y *= SCALE; p1.z *= SCALE; p1.w *= SCALE;
    p2.x *= SCALE; p2.y *= SCALE; p2.z *= SCALE; p2.w *= SCALE;
    pa.x *= SCALE; pa.y *= SCALE; pa.z *= SCALE; pa.w *= SCALE;

    float z1 = 0.f, z2 = 0.f, z3 = 0.f;
    float hd1[4] = {0, 0, 0, 0}, hd2[4] = {0, 0, 0, 0}, ha4[4] = {0, 0, 0, 0};
    float sd1[4] = {0, 0, 0, 0}, sd2[4] = {0, 0, 0, 0}, sa4[4] = {0, 0, 0, 0};

    if (r0 < r1) {
        int last = r1 - 1;
        int sN = ldg_pol4i(&g_esrc[r0], polF);
        const __half* kvp = &g_kvh[(long long)sN * 640];
        uint2 k1u = ldg_pol8(kvp + f, polL);
        uint2 k2u = ldg_pol8(kvp + 128 + f, polL);
        uint2 kau = ldg_pol8(kvp + 256 + f, polL);
        uint2 vdu = ldg_pol8(kvp + 384 + f, polL);
        uint2 vau = ldg_pol8(kvp + 512 + f, polL);
        uint2 eau = ldg_pol8(&g_eas[(long long)r0 * 32 + cg * 4], polF);

        for (int idx = r0; idx < r1; idx++) {
            int nx = (idx + 1 <= last) ? idx + 1 : last;
            int sNN = ldg_pol4i(&g_esrc[nx], polF);
            const __half* kvpN = &g_kvh[(long long)sNN * 640];
            uint2 nk1 = ldg_pol8(kvpN + f, polL);
            uint2 nk2 = ldg_pol8(kvpN + 128 + f, polL);
            uint2 nka = ldg_pol8(kvpN + 256 + f, polL);
            uint2 nvd = ldg_pol8(kvpN + 384 + f, polL);
            uint2 nva = ldg_pol8(kvpN + 512 + f, polL);
            uint2 nea = ldg_pol8(&g_eas[(long long)nx * 32 + cg * 4], polF);

            float2 k1a = __half22float2(*(__half2*)&k1u.x), k1b = __half22float2(*(__half2*)&k1u.y);
            float2 k2a = __half22float2(*(__half2*)&k2u.x), k2b = __half22float2(*(__half2*)&k2u.y);
            float2 kaa = __half22float2(*(__half2*)&kau.x), kab = __half22float2(*(__half2*)&kau.y);
            float2 ea0 = __half22float2(*(__half2*)&eau.x), ea1 = __half22float2(*(__half2*)&eau.y);

            float t0 = q1.x * k1a.x + q1.y * k1a.y + q1.z * k1b.x + q1.w * k1b.y
                     + p1.x * ea0.x + p1.y * ea0.y + p1.z * ea1.x + p1.w * ea1.y;
            float t1 = q2.x * k2a.x + q2.y * k2a.y + q2.z * k2b.x + q2.w * k2b.y
                     + p2.x * ea0.x + p2.y * ea0.y + p2.z * ea1.x + p2.w * ea1.y;
            float t2 = qa.x * kaa.x + qa.y * kaa.y + qa.z * kab.x + qa.w * kab.y
                     + pa.x * ea0.x + pa.y * ea0.y + pa.z * ea1.x + pa.w * ea1.y;
#pragma unroll
            for (int off = 1; off < 8; off <<= 1) {
                t0 += __shfl_xor_sync(0xffffffffu, t0, off);
                t1 += __shfl_xor_sync(0xffffffffu, t1, off);
                t2 += __shfl_xor_sync(0xffffffffu, t2, off);
            }
            float e1 = __expf(t0), e2 = __expf(t1), e3 = __expf(t2);
            z1 += e1; z2 += e2; z3 += e3;

            float2 vda = __half22float2(*(__half2*)&vdu.x), vdb = __half22float2(*(__half2*)&vdu.y);
            float2 vaa = __half22float2(*(__half2*)&vau.x), vab = __half22float2(*(__half2*)&vau.y);

            hd1[0] = fmaf(vda.x, e1, hd1[0]); hd1[1] = fmaf(vda.y, e1, hd1[1]);
            hd1[2] = fmaf(vdb.x, e1, hd1[2]); hd1[3] = fmaf(vdb.y, e1, hd1[3]);
            hd2[0] = fmaf(vda.x, e2, hd2[0]); hd2[1] = fmaf(vda.y, e2, hd2[1]);
            hd2[2] = fmaf(vdb.x, e2, hd2[2]); hd2[3] = fmaf(vdb.y, e2, hd2[3]);
            ha4[0] = fmaf(vaa.x, e3, ha4[0]); ha4[1] = fmaf(vaa.y, e3, ha4[1]);
            ha4[2] = fmaf(vab.x, e3, ha4[2]); ha4[3] = fmaf(vab.y, e3, ha4[3]);
            sd1[0] = fmaf(ea0.x, e1, sd1[0]); sd1[1] = fmaf(ea0.y, e1, sd1[1]);
            sd1[2] = fmaf(ea1.x, e1, sd1[2]); sd1[3] = fmaf(ea1.y, e1, sd1[3]);
            sd2[0] = fmaf(ea0.x, e2, sd2[0]); sd2[1] = fmaf(ea0.y, e2, sd2[1]);
            sd2[2] = fmaf(ea1.x, e2, sd2[2]); sd2[3] = fmaf(ea1.y, e2, sd2[3]);
            sa4[0] = fmaf(ea0.x, e3, sa4[0]); sa4[1] = fmaf(ea0.y, e3, sa4[1]);
            sa4[2] = fmaf(ea1.x, e3, sa4[2]); sa4[3] = fmaf(ea1.y, e3, sa4[3]);

            k1u = nk1; k2u = nk2; kau = nka; vdu = nvd; vau = nva; eau = nea;
        }
    }

    float i1n = 1.f / (z1 + 1e-16f);
    float i2l = lam / (z2 + 1e-16f);
    float i3n = 1.f / (z3 + 1e-16f);

    float hd[4], ha[4], sd[4], sa[4];
#pragma unroll
    for (int i = 0; i < 4; i++) {
        hd[i] = hd1[i] * i1n - hd2[i] * i2l;
        sd[i] = sd1[i] * i1n - sd2[i] * i2l;
        ha[i] = ha4[i] * i3n;
        sa[i] = sa4[i] * i3n;
    }

    *(float4*)&sbuf[wslot][h * 36 + cg * 4] = make_float4(sd[0], sd[1], sd[2], sd[3]);
    *(float4*)&sbuf[wslot][144 + h * 36 + cg * 4] = make_float4(sa[0], sa[1], sa[2], sa[3]);
    __syncwarp();

    const float* sdp = &sbuf[wslot][h * 36];
    const float* sap = &sbuf[wslot][144 + h * 36];
    float ud[4], ua[4];
#pragma unroll
    for (int i = 0; i < 4; i++) { ud[i] = hd[i]; ua[i] = ha[i]; }
#pragma unroll
    for (int i = 0; i < 4; i++) {
        const float4* wd = (const float4*)&Wvrd[(f + i) * 32];
        const float4* wa = (const float4*)&Wvra[(f + i) * 32];
        float accd = 0.f, acca = 0.f;
#pragma unroll
        for (int q = 0; q < 8; q++) {
            float4 w4 = __ldg(&wd[q]);
            float4 s4 = *(const float4*)&sdp[q * 4];
            accd += w4.x * s4.x + w4.y * s4.y + w4.z * s4.z + w4.w * s4.w;
            float4 w4a = __ldg(&wa[q]);
            float4 s4a = *(const float4*)&sap[q * 4];
            acca += w4a.x * s4a.x + w4a.y * s4a.y + w4a.z * s4a.z + w4a.w * s4a.w;
        }
        ud[i] += accd; ua[i] += acca;
    }
    stg_cs16(&g_ud[d * 128 + f], make_float4(ud[0], ud[1], ud[2], ud[3]));
    stg_cs16(&g_ua[d * 128 + f], make_float4(ua[0], ua[1], ua[2], ua[3]));
}

// ---------------- final HMMA ----------------
#define F_AH 0
#define F_AL 32768
#define F_WH 65536
#define F_WL 98304
#define F_STAGE 131072
#define F_STRIDE 132
#define F_TOTAL (F_STAGE + 128 * F_STRIDE * 4)

__global__ __launch_bounds__(256, 1) void k_final_hmma(
    const float* __restrict__ bproj, const float* __restrict__ rms_w,
    float* __restrict__ out) {
    extern __shared__ char smem[];
    uint32_t sb = smem_to_u32(smem);
    float* stage = (float*)(smem + F_STAGE);
    int tid = threadIdx.x;
    int wid = tid >> 5, lane = tid & 31;
    int n0blk = blockIdx.x * 128;
    int m0 = (wid & 3) * 32;
    int n0 = (wid >> 2) * 64;

    float acc[2][8][4];
#pragma unroll
    for (int i = 0; i < 2; i++)
#pragma unroll
        for (int j = 0; j < 8; j++)
#pragma unroll
            for (int q = 0; q < 4; q++) acc[i][j][q] = 0.f;

    for (int kh = 0; kh < 2; kh++) {
        const float* A = kh ? g_ua : g_ud;
        for (int u = tid; u < 4096; u += 256) {
            int row = u >> 5, c4 = (u & 31) << 2;
            float4 fv = make_float4(0.f, 0.f, 0.f, 0.f);
            if (n0blk + row < NN) fv = *(const float4*)&A[(long long)(n0blk + row) * 128 + c4];
            dec_store(smem + F_AH, smem + F_AL, row, c4, fv);
        }
        for (int u = tid; u < 4096; u += 256) {
            int row = u >> 5, c4 = (u & 31) << 2;
            float4 fv = *(const float4*)&g_Wc[row * 256 + kh * 128 + c4];
            dec_store(smem + F_WH, smem + F_WL, row, c4, fv);
        }
        __syncthreads();
        mma_block(sb + F_AH, sb + F_AL, sb + F_WH, sb + F_WL, m0, n0, lane, acc);
        __syncthreads();
    }
#pragma unroll
    for (int mi = 0; mi < 2; mi++)
#pragma unroll
        for (int ni = 0; ni < 8; ni++) {
            int row = m0 + mi * 16 + (lane >> 2);
            int col = n0 + ni * 8 + (lane & 3) * 2;
            stage[row * F_STRIDE + col]     = acc[mi][ni][0];
            stage[row * F_STRIDE + col + 1] = acc[mi][ni][1];
            stage[(row + 8) * F_STRIDE + col]     = acc[mi][ni][2];
            stage[(row + 8) * F_STRIDE + col + 1] = acc[mi][ni][3];
        }
    __syncthreads();

    float4 bp = *(const float4*)&bproj[lane * 4];
    float4 rw = *(const float4*)&rms_w[lane * 4];
#pragma unroll 1
    for (int rr = 0; rr < 16; rr++) {
        int r = wid * 16 + rr;
        int n = n0blk + r;
        float4 v = *(float4*)&stage[r * F_STRIDE + lane * 4];
        float4 xi = make_float4(0.f, 0.f, 0.f, 0.f);
        if (n < NN) xi = *(const float4*)&g_nf[(6ll * NN + n) * 128 + lane * 4];
        v.x += bp.x + xi.x; v.y += bp.y + xi.y;
        v.z += bp.z + xi.z; v.w += bp.w + xi.w;
        float ss = v.x * v.x + v.y * v.y + v.z * v.z + v.w * v.w;
#pragma unroll
        for (int off = 16; off > 0; off >>= 1)
            ss += __shfl_xor_sync(0xffffffffu, ss, off);
        float rn = rsqrtf(ss * (1.f / 128.f) + 1e-6f);
        if (n < NN) {
            float4 o = make_float4(v.x * rn * rw.x, v.y * rn * rw.y,
                                   v.z * rn * rw.z, v.w * rn * rw.w);
            *(float4*)&out[(long long)n * 128 + lane * 4] = o;
        }
    }
}

// ---------------- launch ----------------
extern "C" void kernel_launch(void* const* d_in, const int* in_sizes, int n_in,
                              void* d_out, int out_size) {
    const float* x     = (const float*)d_in[0];
    const int*   ei    = (const int*)d_in[1];
    const float* ea    = (const float*)d_in[2];
    const float* Wq1   = (const float*)d_in[3];
    const float* Wq2   = (const float*)d_in[4];
    const float* Wk1   = (const float*)d_in[5];
    const float* Wk2   = (const float*)d_in[6];
    const float* Wvd   = (const float*)d_in[7];
    const float* Wkr1  = (const float*)d_in[8];
    const float* Wkr2  = (const float*)d_in[9];
    const float* Wvrd  = (const float*)d_in[10];
    const float* Woutd = (const float*)d_in[11];
    const float* lam   = (const float*)d_in[12];
    const float* Wqa   = (const float*)d_in[13];
    const float* Wka   = (const float*)d_in[14];
    const float* Wva   = (const float*)d_in[15];
    const float* Wkra  = (const float*)d_in[16];
    const float* Wvra  = (const float*)d_in[17];
    const float* Wouta = (const float*)d_in[18];
    const float* Wproj = (const float*)d_in[19];
    const float* bproj = (const float*)d_in[20];
    const float* Win   = (const float*)d_in[21];
    const float* b_in  = (const float*)d_in[22];
    const float* rms_w = (const float*)d_in[23];
    float* out = (float*)d_out;

    int mtile = (NN + 127) / 128;  // 391

    cudaFuncSetAttribute(k_nodeproj_hmma, cudaFuncAttributeMaxDynamicSharedMemorySize, NP_TOTAL);
    cudaFuncSetAttribute(k_final_hmma, cudaFuncAttributeMaxDynamicSharedMemorySize, F_TOTAL);

    // 1: hist + scan + decw(+M)   2: nodeproj   3: scatter+easort   4: edge (PROFILED)
    k_mix<<<HB + DB, 1024>>>(ei, Wq1, Wq2, Wqa, Wk1, Wk2, Wka, Wvd, Wva, Win,
                             Wkr1, Wkr2, Wkra);
    k_nodeproj_hmma<<<mtile, 256, NP_TOTAL>>>(x, b_in);
    k_scatter_easort<<<(NE + 255) / 256, 256>>>(ei, ea);
    k_edge<<<(NN * 32 + 255) / 256, 256>>>(lam, Wvrd, Wvra);
    k_compose2<<<(2 * HC * HC + 255) / 256, 256>>>(Wproj, Woutd, Wouta);
    k_final_hmma<<<mtile, 256, F_TOTAL>>>(bproj, rms_w, out);
}